// round 2
// baseline (speedup 1.0000x reference)
#include <cuda_runtime.h>
#include <cstdint>

#define BB 8
#define CC 16
#define FDIM 256
#define F2 129
#define TT 512
#define C2 32
#define HH 16
#define NT (BB*TT)

// ---------------- device scratch ----------------
__device__ float g_zraw[(size_t)BB*C2*F2*TT];   // spectrum planes (b, c2, k, t): re c=0..15, im c=16..31
__device__ float g_pre [(size_t)NT*F2*128];     // gate preactivations (n, k, 128): [dir*64 + row]
__device__ float g_h   [(size_t)NT*F2*C2];      // LSTM hidden cat(fwd,bwd): (n, k, 2H)
__device__ float g_P   [(size_t)BB*C2*F2*TT];   // product spectrum planes
__device__ float g_mean[NT];
__device__ float g_rstd[NT];
__device__ float g_psum[NT*6];
__device__ float g_psq [NT*6];

__device__ __forceinline__ float sigf(float x) {
    return __fdividef(1.f, 1.f + __expf(-x));
}
__device__ __forceinline__ float tanhfast(float x) {
    return fmaf(2.f, __fdividef(1.f, 1.f + __expf(-2.f * x)), -1.f);
}
__device__ __forceinline__ unsigned long long pack2(float a, float b) {
    unsigned long long r;
    asm("mov.b64 %0, {%1,%2};" : "=l"(r) : "r"(__float_as_uint(a)), "r"(__float_as_uint(b)));
    return r;
}
__device__ __forceinline__ void unpack2(unsigned long long v, float& a, float& b) {
    unsigned int lo, hi;
    asm("mov.b64 {%0,%1}, %2;" : "=r"(lo), "=r"(hi) : "l"(v));
    a = __uint_as_float(lo); b = __uint_as_float(hi);
}
__device__ __forceinline__ unsigned long long ffma2(unsigned long long a, unsigned long long b, unsigned long long c) {
    unsigned long long d;
    asm("fma.rn.f32x2 %0, %1, %2, %3;" : "=l"(d) : "l"(a), "l"(b), "l"(c));
    return d;
}

// ---------------- K1: forward rfft, warp-per-column DIF -------------------
// grid (128, 32), block 512 (16 warps = 16 t-columns)
__global__ void __launch_bounds__(512) k_fft_fwd(const float* __restrict__ x) {
    int bc = blockIdx.x;
    int t0 = blockIdx.y * 16;
    int b = bc >> 4, c = bc & 15;
    __shared__ float sr[256][17], si[256][17];
    __shared__ float twr[128], twi[128];
    int tid = threadIdx.x;

    if (tid < 128) {
        float sv, cv;
        __sincosf(-6.28318530717958647692f * (float)tid * (1.f / 256.f), &sv, &cv);
        twr[tid] = cv; twi[tid] = sv;
    }
    for (int i = tid; i < 256 * 16; i += 512) {
        int f = i >> 4, tt = i & 15;
        sr[f][tt] = x[((size_t)bc * 256 + f) * 512 + t0 + tt];
        si[f][tt] = 0.f;
    }
    __syncthreads();

    int w = tid >> 5, l = tid & 31;
    #pragma unroll
    for (int s = 8; s >= 1; --s) {
        int hm = 1 << (s - 1);
        #pragma unroll
        for (int tloc = 0; tloc < 4; ++tloc) {
            int bfy = l + 32 * tloc;
            int g = bfy >> (s - 1), p = bfy & (hm - 1);
            int idx = (g << s) + p;
            int j = p << (8 - s);
            float cv = twr[j], sv = twi[j];
            float ar = sr[idx][w],      ai = si[idx][w];
            float br = sr[idx + hm][w], bi = si[idx + hm][w];
            float dr = ar - br, di = ai - bi;
            sr[idx][w] = ar + br;  si[idx][w] = ai + bi;
            sr[idx + hm][w] = dr * cv - di * sv;
            si[idx + hm][w] = dr * sv + di * cv;
        }
        __syncwarp();
    }
    __syncthreads();

    for (int i = tid; i < 129 * 16; i += 512) {
        int k = i >> 4, tt = i & 15;
        int src = __brev((unsigned)k) >> 24;
        g_zraw[(((size_t)b * 32 + c)      * 129 + k) * 512 + t0 + tt] = sr[src][tt];
        g_zraw[(((size_t)b * 32 + 16 + c) * 129 + k) * 512 + t0 + tt] = si[src][tt];
    }
}

// ---------------- K2a: partial stats, grid (8,16,6), block 512 --------------
__global__ void k_stats1() {
    __shared__ float s_sum[16][32], s_sq[16][32];
    int w = threadIdx.x >> 5, l = threadIdx.x & 31;
    int b = blockIdx.x;
    int t = blockIdx.y * 32 + l;
    int part = blockIdx.z;
    const float* base = g_zraw + (size_t)b * 4128 * 512 + t;
    float sum = 0.f, sq = 0.f;
    int e0 = part * 688 + w * 43;
    #pragma unroll 4
    for (int e = e0; e < e0 + 43; ++e) {
        float v = base[(size_t)e * 512];
        sum += v; sq = fmaf(v, v, sq);
    }
    s_sum[w][l] = sum; s_sq[w][l] = sq;
    __syncthreads();
    if (threadIdx.x < 32) {
        int n = b * 512 + blockIdx.y * 32 + threadIdx.x;
        float S = 0.f, Q = 0.f;
        #pragma unroll
        for (int i = 0; i < 16; ++i) { S += s_sum[i][threadIdx.x]; Q += s_sq[i][threadIdx.x]; }
        g_psum[n * 6 + part] = S;
        g_psq [n * 6 + part] = Q;
    }
}

// ---------------- K2b: finalize stats, grid 16, block 256 -------------------
__global__ void k_stats2() {
    int n = blockIdx.x * 256 + threadIdx.x;
    float S = 0.f, Q = 0.f;
    #pragma unroll
    for (int p = 0; p < 6; ++p) { S += g_psum[n * 6 + p]; Q += g_psq[n * 6 + p]; }
    float mean = S * (1.f / 4128.f);
    float var = (Q - S * mean) * (1.f / 4127.f);
    g_mean[n] = mean;
    g_rstd[n] = __fdividef(1.f, sqrtf(fmaxf(var, 0.f)) + 1e-8f);
}

// ---------------- K3: normalize + input-gate GEMM (f32x2 packed) ------------
// grid (129, 16, 8), block 256
__global__ void __launch_bounds__(256) k_norm_gates(
    const float* __restrict__ nw, const float* __restrict__ nb,
    const float* __restrict__ wihf, const float* __restrict__ bihf, const float* __restrict__ bhhf,
    const float* __restrict__ wihb, const float* __restrict__ bihb, const float* __restrict__ bhhb) {
    int k = blockIdx.x, t0 = blockIdx.y * 32, b = blockIdx.z;
    int n0 = b * 512 + t0;
    __shared__ float zs[32][34];         // [c2][t]
    __shared__ float nws[32], nbs[32], means[32], rstds[32];
    int tid = threadIdx.x;

    if (tid < 32) {
        nws[tid] = nw[tid * 129 + k];
        nbs[tid] = nb[tid * 129 + k];
        means[tid] = g_mean[n0 + tid];
        rstds[tid] = g_rstd[n0 + tid];
    }
    for (int i = tid; i < 1024; i += 256) {
        int c2 = i >> 5, tt = i & 31;
        zs[c2][tt] = g_zraw[(((size_t)b * 32 + c2) * 129 + k) * 512 + t0 + tt];
    }
    __syncthreads();
    for (int i = tid; i < 1024; i += 256) {
        int c2 = i >> 5, tt = i & 31;
        zs[c2][tt] = (zs[c2][tt] - means[tt]) * rstds[tt] * nws[c2] + nbs[c2];
    }
    __syncthreads();

    int g = tid & 127;                   // gate slot 0..127
    int th = tid >> 7;                   // t-half
    int dir = g >> 6, row = g & 63;
    const float* wih = dir ? wihb : wihf;
    float bias = dir ? (bihb[row] + bhhb[row]) : (bihf[row] + bhhf[row]);

    unsigned long long wp[32];
    #pragma unroll
    for (int q = 0; q < 32; ++q) {
        float wv = wih[row * 32 + q];
        wp[q] = pack2(wv, wv);
    }
    unsigned long long bb = pack2(bias, bias);

    #pragma unroll 2
    for (int pair = 0; pair < 8; ++pair) {
        int t2 = th * 16 + pair * 2;
        unsigned long long acc = bb;
        #pragma unroll
        for (int q = 0; q < 32; ++q) {
            unsigned long long y2 = *reinterpret_cast<const unsigned long long*>(&zs[q][t2]);
            acc = ffma2(y2, wp[q], acc);
        }
        float v0, v1; unpack2(acc, v0, v1);
        g_pre[((size_t)(n0 + t2)     * 129 + k) * 128 + g] = v0;
        g_pre[((size_t)(n0 + t2 + 1) * 129 + k) * 128 + g] = v1;
    }
}

// ---------------- K4: recurrent-only LSTM, one warp per (seq, dir) ----------
__global__ void __launch_bounds__(256) k_lstm(
    const float* __restrict__ whhf, const float* __restrict__ whhb) {
    int wg = blockIdx.x * 8 + (threadIdx.x >> 5);
    int lane = threadIdx.x & 31;
    int n = wg >> 1, dir = wg & 1;

    const float* whh = dir ? whhb : whhf;
    float wh0[16], wh1[16];
    #pragma unroll
    for (int q = 0; q < 16; ++q) {
        wh0[q] = whh[lane * 16 + q];
        wh1[q] = whh[(lane + 32) * 16 + q];
    }

    const float* pbase = g_pre + (size_t)n * 129 * 128 + dir * 64;
    float* hbase = g_h + (size_t)n * 129 * 32 + dir * 16;

    float h = 0.f, cst = 0.f;
    int k = dir ? 128 : 0;
    int stepd = dir ? -1 : 1;
    float p0 = pbase[k * 128 + lane];
    float p1 = pbase[k * 128 + 32 + lane];

    for (int s = 0; s < 129; ++s) {
        int kn = k + stepd;
        float np0 = 0.f, np1 = 0.f;
        if (s < 128) {
            np0 = pbase[kn * 128 + lane];
            np1 = pbase[kn * 128 + 32 + lane];
        }
        float a0 = p0, a1 = p1;
        #pragma unroll
        for (int q = 0; q < 16; ++q) {
            float hv = __shfl_sync(0xffffffffu, h, q);
            a0 = fmaf(hv, wh0[q], a0);
            a1 = fmaf(hv, wh1[q], a1);
        }
        float fo0 = __shfl_xor_sync(0xffffffffu, a0, 16);
        float fo1 = __shfl_xor_sync(0xffffffffu, a1, 16);
        if (lane < 16) {
            float ig = sigf(a0);
            float gg = tanhfast(a1);
            float ff = sigf(fo0);
            float oo = sigf(fo1);
            cst = fmaf(ff, cst, ig * gg);
            h = oo * tanhfast(cst);
            hbase[k * 32 + lane] = h;
        }
        p0 = np0; p1 = np1; k = kn;
    }
}

// ---------------- K5: linear(2H->2C) + complex multiply ---------------------
__global__ void k_lin_cmul(const float* __restrict__ lw, const float* __restrict__ lb) {
    int k = blockIdx.x, t0 = blockIdx.y * 32, b = blockIdx.z;
    __shared__ float hs[32][33];    // [t][j]
    __shared__ float lws[32][32];   // [c2][j]
    __shared__ float lbs[32];
    __shared__ float yls[32][33];   // [c2][t]
    int tid = threadIdx.x;

    for (int i = tid; i < 1024; i += 256) lws[i >> 5][i & 31] = lw[i];
    if (tid < 32) lbs[tid] = lb[tid];
    for (int i = tid; i < 1024; i += 256) {
        int tt = i >> 5, j = i & 31;
        hs[tt][j] = g_h[(((size_t)(b * 512 + t0 + tt)) * 129 + k) * 32 + j];
    }
    __syncthreads();

    int tt = tid & 31, g = tid >> 5;
    #pragma unroll
    for (int ci = 0; ci < 4; ++ci) {
        int c2 = g + ci * 8;
        float acc = lbs[c2];
        #pragma unroll
        for (int j = 0; j < 32; ++j) acc = fmaf(hs[tt][j], lws[c2][j], acc);
        yls[c2][tt] = acc;
    }
    __syncthreads();

    size_t basez = ((size_t)(b * 32) * 129 + k) * 512 + t0 + tt;
    const size_t ps = (size_t)129 * 512;
    #pragma unroll
    for (int ci = 0; ci < 4; ++ci) {
        int c2 = g + ci * 8;
        if (c2 < 16) {
            float xr = g_zraw[basez + (size_t)c2 * ps];
            float xi = g_zraw[basez + (size_t)(c2 + 16) * ps];
            float yr = yls[c2][tt], yi = yls[c2 + 16][tt];
            g_P[basez + (size_t)c2 * ps] = yr * xr - yi * xi;
        } else {
            int c = c2 - 16;
            float xr = g_zraw[basez + (size_t)c * ps];
            float xi = g_zraw[basez + (size_t)c2 * ps];
            float yr = yls[c][tt], yi = yls[c2][tt];
            g_P[basez + (size_t)c2 * ps] = yr * xi + yi * xr;
        }
    }
}

// ---------------- K6: irfft, warp-per-column inverse DIF --------------------
// grid (128, 32), block 512
__global__ void __launch_bounds__(512) k_fft_inv(float* __restrict__ out) {
    int bc = blockIdx.x;
    int t0 = blockIdx.y * 16;
    int b = bc >> 4, c = bc & 15;
    __shared__ float sr[256][17], si[256][17];
    __shared__ float twr[128], twi[128];
    int tid = threadIdx.x;

    if (tid < 128) {
        float sv, cv;
        __sincosf(6.28318530717958647692f * (float)tid * (1.f / 256.f), &sv, &cv);
        twr[tid] = cv; twi[tid] = sv;
    }
    for (int i = tid; i < 129 * 16; i += 512) {
        int k = i >> 4, tt = i & 15;
        sr[k][tt] = g_P[(((size_t)b * 32 + c)      * 129 + k) * 512 + t0 + tt];
        si[k][tt] = g_P[(((size_t)b * 32 + 16 + c) * 129 + k) * 512 + t0 + tt];
    }
    __syncthreads();
    // Hermitian extension: rows 129..255 from rows 127..1
    for (int i = tid; i < 127 * 16; i += 512) {
        int j = 129 + (i >> 4), tt = i & 15;
        sr[j][tt] = sr[256 - j][tt];
        si[j][tt] = -si[256 - j][tt];
    }
    __syncthreads();

    int w = tid >> 5, l = tid & 31;
    #pragma unroll
    for (int s = 8; s >= 1; --s) {
        int hm = 1 << (s - 1);
        #pragma unroll
        for (int tloc = 0; tloc < 4; ++tloc) {
            int bfy = l + 32 * tloc;
            int g = bfy >> (s - 1), p = bfy & (hm - 1);
            int idx = (g << s) + p;
            int j = p << (8 - s);
            float cv = twr[j], sv = twi[j];
            float ar = sr[idx][w],      ai = si[idx][w];
            float br = sr[idx + hm][w], bi = si[idx + hm][w];
            float dr = ar - br, di = ai - bi;
            sr[idx][w] = ar + br;  si[idx][w] = ai + bi;
            sr[idx + hm][w] = dr * cv - di * sv;
            si[idx + hm][w] = dr * sv + di * cv;
        }
        __syncwarp();
    }
    __syncthreads();

    const float inv = 1.f / 256.f;
    for (int i = tid; i < 256 * 16; i += 512) {
        int f = i >> 4, tt = i & 15;
        int src = __brev((unsigned)f) >> 24;
        out[((size_t)bc * 256 + f) * 512 + t0 + tt] = sr[src][tt] * inv;
    }
}

// ---------------- launcher ---------------------------------------------------
extern "C" void kernel_launch(void* const* d_in, const int* in_sizes, int n_in,
                              void* d_out, int out_size) {
    const float* x    = (const float*)d_in[0];
    const float* nw   = (const float*)d_in[1];
    const float* nb   = (const float*)d_in[2];
    const float* wihf = (const float*)d_in[3];
    const float* whhf = (const float*)d_in[4];
    const float* bihf = (const float*)d_in[5];
    const float* bhhf = (const float*)d_in[6];
    const float* wihb = (const float*)d_in[7];
    const float* whhb = (const float*)d_in[8];
    const float* bihb = (const float*)d_in[9];
    const float* bhhb = (const float*)d_in[10];
    const float* lw   = (const float*)d_in[11];
    const float* lb   = (const float*)d_in[12];
    float* out = (float*)d_out;

    k_fft_fwd<<<dim3(128, 32), 512>>>(x);
    k_stats1<<<dim3(8, 16, 6), 512>>>();
    k_stats2<<<16, 256>>>();
    k_norm_gates<<<dim3(129, 16, 8), 256>>>(nw, nb, wihf, bihf, bhhf, wihb, bihb, bhhb);
    k_lstm<<<1024, 256>>>(whhf, whhb);
    k_lin_cmul<<<dim3(129, 16, 8), 256>>>(lw, lb);
    k_fft_inv<<<dim3(128, 32), 512>>>(out);
}

// round 3
// speedup vs baseline: 1.5726x; 1.5726x over previous
#include <cuda_runtime.h>
#include <cstdint>

#define BB 8
#define CC 16
#define FDIM 256
#define F2 129
#define TT 512
#define C2 32
#define HH 16
#define NT (BB*TT)

// ---------------- device scratch ----------------
__device__ float g_zraw[(size_t)BB*C2*F2*TT];   // spectrum planes (b, c2, k, t): re c=0..15, im c=16..31
__device__ float g_pre [(size_t)NT*F2*128];     // gate preactivations (n, k, 128): [dir*64 + row]
__device__ float g_h   [(size_t)NT*F2*C2];      // LSTM hidden cat(fwd,bwd): (n, k, 2H)
__device__ float g_P   [(size_t)BB*C2*F2*TT];   // product spectrum planes
__device__ float g_mean[NT];
__device__ float g_rstd[NT];
__device__ float g_psum[NT*6];
__device__ float g_psq [NT*6];

__device__ __forceinline__ float sigf(float x) {
    return __fdividef(1.f, 1.f + __expf(-x));
}
__device__ __forceinline__ float tanhfast(float x) {
    return fmaf(2.f, __fdividef(1.f, 1.f + __expf(-2.f * x)), -1.f);
}
__device__ __forceinline__ unsigned long long pack2(float a, float b) {
    unsigned long long r;
    asm("mov.b64 %0, {%1,%2};" : "=l"(r) : "r"(__float_as_uint(a)), "r"(__float_as_uint(b)));
    return r;
}
__device__ __forceinline__ void unpack2(unsigned long long v, float& a, float& b) {
    unsigned int lo, hi;
    asm("mov.b64 {%0,%1}, %2;" : "=r"(lo), "=r"(hi) : "l"(v));
    a = __uint_as_float(lo); b = __uint_as_float(hi);
}
__device__ __forceinline__ unsigned long long ffma2(unsigned long long a, unsigned long long b, unsigned long long c) {
    unsigned long long d;
    asm("fma.rn.f32x2 %0, %1, %2, %3;" : "=l"(d) : "l"(a), "l"(b), "l"(c));
    return d;
}

// ---------------- K1: forward rfft, warp-per-column DIF -------------------
// grid (128, 32), block 512 (16 warps = 16 t-columns)
__global__ void __launch_bounds__(512) k_fft_fwd(const float* __restrict__ x) {
    int bc = blockIdx.x;
    int t0 = blockIdx.y * 16;
    int b = bc >> 4, c = bc & 15;
    __shared__ float sr[256][17], si[256][17];
    __shared__ float twr[128], twi[128];
    int tid = threadIdx.x;

    if (tid < 128) {
        float sv, cv;
        __sincosf(-6.28318530717958647692f * (float)tid * (1.f / 256.f), &sv, &cv);
        twr[tid] = cv; twi[tid] = sv;
    }
    for (int i = tid; i < 256 * 16; i += 512) {
        int f = i >> 4, tt = i & 15;
        sr[f][tt] = x[((size_t)bc * 256 + f) * 512 + t0 + tt];
        si[f][tt] = 0.f;
    }
    __syncthreads();

    int w = tid >> 5, l = tid & 31;
    #pragma unroll
    for (int s = 8; s >= 1; --s) {
        int hm = 1 << (s - 1);
        #pragma unroll
        for (int tloc = 0; tloc < 4; ++tloc) {
            int bfy = l + 32 * tloc;
            int g = bfy >> (s - 1), p = bfy & (hm - 1);
            int idx = (g << s) + p;
            int j = p << (8 - s);
            float cv = twr[j], sv = twi[j];
            float ar = sr[idx][w],      ai = si[idx][w];
            float br = sr[idx + hm][w], bi = si[idx + hm][w];
            float dr = ar - br, di = ai - bi;
            sr[idx][w] = ar + br;  si[idx][w] = ai + bi;
            sr[idx + hm][w] = dr * cv - di * sv;
            si[idx + hm][w] = dr * sv + di * cv;
        }
        __syncwarp();
    }
    __syncthreads();

    for (int i = tid; i < 129 * 16; i += 512) {
        int k = i >> 4, tt = i & 15;
        int src = __brev((unsigned)k) >> 24;
        g_zraw[(((size_t)b * 32 + c)      * 129 + k) * 512 + t0 + tt] = sr[src][tt];
        g_zraw[(((size_t)b * 32 + 16 + c) * 129 + k) * 512 + t0 + tt] = si[src][tt];
    }
}

// ---------------- K2a: partial stats, grid (8,16,6), block 512 --------------
__global__ void k_stats1() {
    __shared__ float s_sum[16][32], s_sq[16][32];
    int w = threadIdx.x >> 5, l = threadIdx.x & 31;
    int b = blockIdx.x;
    int t = blockIdx.y * 32 + l;
    int part = blockIdx.z;
    const float* base = g_zraw + (size_t)b * 4128 * 512 + t;
    float sum = 0.f, sq = 0.f;
    int e0 = part * 688 + w * 43;
    #pragma unroll 4
    for (int e = e0; e < e0 + 43; ++e) {
        float v = base[(size_t)e * 512];
        sum += v; sq = fmaf(v, v, sq);
    }
    s_sum[w][l] = sum; s_sq[w][l] = sq;
    __syncthreads();
    if (threadIdx.x < 32) {
        int n = b * 512 + blockIdx.y * 32 + threadIdx.x;
        float S = 0.f, Q = 0.f;
        #pragma unroll
        for (int i = 0; i < 16; ++i) { S += s_sum[i][threadIdx.x]; Q += s_sq[i][threadIdx.x]; }
        g_psum[n * 6 + part] = S;
        g_psq [n * 6 + part] = Q;
    }
}

// ---------------- K2b: finalize stats, grid 16, block 256 -------------------
__global__ void k_stats2() {
    int n = blockIdx.x * 256 + threadIdx.x;
    float S = 0.f, Q = 0.f;
    #pragma unroll
    for (int p = 0; p < 6; ++p) { S += g_psum[n * 6 + p]; Q += g_psq[n * 6 + p]; }
    float mean = S * (1.f / 4128.f);
    float var = (Q - S * mean) * (1.f / 4127.f);
    g_mean[n] = mean;
    g_rstd[n] = __fdividef(1.f, sqrtf(fmaxf(var, 0.f)) + 1e-8f);
}

// ---------------- K3: normalize + input-gate GEMM, register-blocked ---------
// grid (129, 64), block 256. Each block: one k, 64 t-points, all 128 gates.
// Thread tile: 8 gates x 4 t. Weights pre-packed (w,w) in smem; y as f32x2.
__global__ void __launch_bounds__(256) k_gates(
    const float* __restrict__ nw, const float* __restrict__ nb,
    const float* __restrict__ wihf, const float* __restrict__ bihf, const float* __restrict__ bhhf,
    const float* __restrict__ wihb, const float* __restrict__ bihb, const float* __restrict__ bhhb) {
    int k = blockIdx.x;
    int n0 = blockIdx.y * 64;
    int b = n0 >> 9, tl0 = n0 & 511;
    __shared__ __align__(16) float ys[32][68];                 // [q][t]
    __shared__ __align__(16) union {
        unsigned long long w[32][130];                          // packed weights (w,w): [q][gate]
        float stage[64][132];                                   // output staging [t][gate]
    } u;
    __shared__ float nws[32], nbs[32], means[64], rstds[64], bs[128];
    int tid = threadIdx.x;

    // phase A: load z tile, weights, params
    for (int i = tid; i < 2048; i += 256) {
        int c2 = i >> 6, tt = i & 63;
        ys[c2][tt] = g_zraw[(((size_t)b * 32 + c2) * 129 + k) * 512 + tl0 + tt];
    }
    for (int i = tid; i < 2048; i += 256) {
        int r = i >> 5, q = i & 31;
        float wf = wihf[i]; u.w[q][r] = pack2(wf, wf);
        float wb = wihb[i]; u.w[q][64 + r] = pack2(wb, wb);
    }
    if (tid < 64) bs[tid] = bihf[tid] + bhhf[tid];
    else if (tid < 128) bs[tid] = bihb[tid - 64] + bhhb[tid - 64];
    if (tid < 32) { nws[tid] = nw[tid * 129 + k]; nbs[tid] = nb[tid * 129 + k]; }
    if (tid >= 32 && tid < 96) { means[tid - 32] = g_mean[n0 + tid - 32]; rstds[tid - 32] = g_rstd[n0 + tid - 32]; }
    __syncthreads();

    // phase B: normalize in place
    for (int i = tid; i < 2048; i += 256) {
        int c2 = i >> 6, tt = i & 63;
        ys[c2][tt] = (ys[c2][tt] - means[tt]) * rstds[tt] * nws[c2] + nbs[c2];
    }
    __syncthreads();

    // phase C: GEMM. thread tile: gates [g0, g0+8) x t [t4, t4+4)
    int gg = tid >> 4, tg = tid & 15;
    int g0 = gg << 3, t4 = tg << 2;
    unsigned long long acc[8][2];
    #pragma unroll
    for (int j = 0; j < 8; ++j) {
        float bj = bs[g0 + j];
        acc[j][0] = pack2(bj, bj);
        acc[j][1] = acc[j][0];
    }
    #pragma unroll 4
    for (int q = 0; q < 32; ++q) {
        ulonglong2 y2 = *reinterpret_cast<const ulonglong2*>(&ys[q][t4]);
        const ulonglong2* wp = reinterpret_cast<const ulonglong2*>(&u.w[q][g0]);
        ulonglong2 w01 = wp[0], w23 = wp[1], w45 = wp[2], w67 = wp[3];
        acc[0][0] = ffma2(y2.x, w01.x, acc[0][0]);  acc[0][1] = ffma2(y2.y, w01.x, acc[0][1]);
        acc[1][0] = ffma2(y2.x, w01.y, acc[1][0]);  acc[1][1] = ffma2(y2.y, w01.y, acc[1][1]);
        acc[2][0] = ffma2(y2.x, w23.x, acc[2][0]);  acc[2][1] = ffma2(y2.y, w23.x, acc[2][1]);
        acc[3][0] = ffma2(y2.x, w23.y, acc[3][0]);  acc[3][1] = ffma2(y2.y, w23.y, acc[3][1]);
        acc[4][0] = ffma2(y2.x, w45.x, acc[4][0]);  acc[4][1] = ffma2(y2.y, w45.x, acc[4][1]);
        acc[5][0] = ffma2(y2.x, w45.y, acc[5][0]);  acc[5][1] = ffma2(y2.y, w45.y, acc[5][1]);
        acc[6][0] = ffma2(y2.x, w67.x, acc[6][0]);  acc[6][1] = ffma2(y2.y, w67.x, acc[6][1]);
        acc[7][0] = ffma2(y2.x, w67.y, acc[7][0]);  acc[7][1] = ffma2(y2.y, w67.y, acc[7][1]);
    }
    __syncthreads();   // everyone done reading u.w

    // phase D: stage outputs (t-major rows, gate contiguous)
    #pragma unroll
    for (int j = 0; j < 8; ++j) {
        float v00, v01, v10, v11;
        unpack2(acc[j][0], v00, v01);
        unpack2(acc[j][1], v10, v11);
        u.stage[t4 + 0][g0 + j] = v00;
        u.stage[t4 + 1][g0 + j] = v01;
        u.stage[t4 + 2][g0 + j] = v10;
        u.stage[t4 + 3][g0 + j] = v11;
    }
    __syncthreads();

    // phase E: coalesced store (128 contiguous floats per (n,k))
    for (int i = tid; i < 2048; i += 256) {
        int tt = i >> 5, g4 = (i & 31) << 2;
        float4 v = *reinterpret_cast<const float4*>(&u.stage[tt][g4]);
        *reinterpret_cast<float4*>(&g_pre[((size_t)(n0 + tt) * 129 + k) * 128 + g4]) = v;
    }
}

// ---------------- K4: recurrent-only LSTM, one warp per (seq, dir) ----------
__global__ void __launch_bounds__(256) k_lstm(
    const float* __restrict__ whhf, const float* __restrict__ whhb) {
    int wg = blockIdx.x * 8 + (threadIdx.x >> 5);
    int lane = threadIdx.x & 31;
    int n = wg >> 1, dir = wg & 1;

    const float* whh = dir ? whhb : whhf;
    float wh0[16], wh1[16];
    #pragma unroll
    for (int q = 0; q < 16; ++q) {
        wh0[q] = whh[lane * 16 + q];
        wh1[q] = whh[(lane + 32) * 16 + q];
    }

    const float* pbase = g_pre + (size_t)n * 129 * 128 + dir * 64;
    float* hbase = g_h + (size_t)n * 129 * 32 + dir * 16;

    float h = 0.f, cst = 0.f;
    int k = dir ? 128 : 0;
    int stepd = dir ? -1 : 1;
    float p0 = pbase[k * 128 + lane];
    float p1 = pbase[k * 128 + 32 + lane];

    for (int s = 0; s < 129; ++s) {
        int kn = k + stepd;
        float np0 = 0.f, np1 = 0.f;
        if (s < 128) {
            np0 = pbase[kn * 128 + lane];
            np1 = pbase[kn * 128 + 32 + lane];
        }
        // split accumulation chains for shorter latency
        float a0 = p0, a1 = p1, c0 = 0.f, c1 = 0.f;
        #pragma unroll
        for (int q = 0; q < 8; ++q) {
            float hv = __shfl_sync(0xffffffffu, h, q);
            a0 = fmaf(hv, wh0[q], a0);
            a1 = fmaf(hv, wh1[q], a1);
        }
        #pragma unroll
        for (int q = 8; q < 16; ++q) {
            float hv = __shfl_sync(0xffffffffu, h, q);
            c0 = fmaf(hv, wh0[q], c0);
            c1 = fmaf(hv, wh1[q], c1);
        }
        a0 += c0; a1 += c1;
        float fo0 = __shfl_xor_sync(0xffffffffu, a0, 16);
        float fo1 = __shfl_xor_sync(0xffffffffu, a1, 16);
        if (lane < 16) {
            float ig = sigf(a0);
            float gg = tanhfast(a1);
            float ff = sigf(fo0);
            float oo = sigf(fo1);
            cst = fmaf(ff, cst, ig * gg);
            h = oo * tanhfast(cst);
            hbase[k * 32 + lane] = h;
        }
        p0 = np0; p1 = np1; k = kn;
    }
}

// ---------------- K5: linear(2H->2C) + complex multiply ---------------------
__global__ void k_lin_cmul(const float* __restrict__ lw, const float* __restrict__ lb) {
    int k = blockIdx.x, t0 = blockIdx.y * 32, b = blockIdx.z;
    __shared__ float hs[32][33];    // [t][j]
    __shared__ float lws[32][32];   // [c2][j]
    __shared__ float lbs[32];
    __shared__ float yls[32][33];   // [c2][t]
    int tid = threadIdx.x;

    for (int i = tid; i < 1024; i += 256) lws[i >> 5][i & 31] = lw[i];
    if (tid < 32) lbs[tid] = lb[tid];
    for (int i = tid; i < 1024; i += 256) {
        int tt = i >> 5, j = i & 31;
        hs[tt][j] = g_h[(((size_t)(b * 512 + t0 + tt)) * 129 + k) * 32 + j];
    }
    __syncthreads();

    int tt = tid & 31, g = tid >> 5;
    #pragma unroll
    for (int ci = 0; ci < 4; ++ci) {
        int c2 = g + ci * 8;
        float acc = lbs[c2];
        #pragma unroll
        for (int j = 0; j < 32; ++j) acc = fmaf(hs[tt][j], lws[c2][j], acc);
        yls[c2][tt] = acc;
    }
    __syncthreads();

    size_t basez = ((size_t)(b * 32) * 129 + k) * 512 + t0 + tt;
    const size_t ps = (size_t)129 * 512;
    #pragma unroll
    for (int ci = 0; ci < 4; ++ci) {
        int c2 = g + ci * 8;
        if (c2 < 16) {
            float xr = g_zraw[basez + (size_t)c2 * ps];
            float xi = g_zraw[basez + (size_t)(c2 + 16) * ps];
            float yr = yls[c2][tt], yi = yls[c2 + 16][tt];
            g_P[basez + (size_t)c2 * ps] = yr * xr - yi * xi;
        } else {
            int c = c2 - 16;
            float xr = g_zraw[basez + (size_t)c * ps];
            float xi = g_zraw[basez + (size_t)c2 * ps];
            float yr = yls[c][tt], yi = yls[c2][tt];
            g_P[basez + (size_t)c2 * ps] = yr * xi + yi * xr;
        }
    }
}

// ---------------- K6: irfft, warp-per-column inverse DIF --------------------
// grid (128, 32), block 512
__global__ void __launch_bounds__(512) k_fft_inv(float* __restrict__ out) {
    int bc = blockIdx.x;
    int t0 = blockIdx.y * 16;
    int b = bc >> 4, c = bc & 15;
    __shared__ float sr[256][17], si[256][17];
    __shared__ float twr[128], twi[128];
    int tid = threadIdx.x;

    if (tid < 128) {
        float sv, cv;
        __sincosf(6.28318530717958647692f * (float)tid * (1.f / 256.f), &sv, &cv);
        twr[tid] = cv; twi[tid] = sv;
    }
    for (int i = tid; i < 129 * 16; i += 512) {
        int k = i >> 4, tt = i & 15;
        sr[k][tt] = g_P[(((size_t)b * 32 + c)      * 129 + k) * 512 + t0 + tt];
        si[k][tt] = g_P[(((size_t)b * 32 + 16 + c) * 129 + k) * 512 + t0 + tt];
    }
    __syncthreads();
    for (int i = tid; i < 127 * 16; i += 512) {
        int j = 129 + (i >> 4), tt = i & 15;
        sr[j][tt] = sr[256 - j][tt];
        si[j][tt] = -si[256 - j][tt];
    }
    __syncthreads();

    int w = tid >> 5, l = tid & 31;
    #pragma unroll
    for (int s = 8; s >= 1; --s) {
        int hm = 1 << (s - 1);
        #pragma unroll
        for (int tloc = 0; tloc < 4; ++tloc) {
            int bfy = l + 32 * tloc;
            int g = bfy >> (s - 1), p = bfy & (hm - 1);
            int idx = (g << s) + p;
            int j = p << (8 - s);
            float cv = twr[j], sv = twi[j];
            float ar = sr[idx][w],      ai = si[idx][w];
            float br = sr[idx + hm][w], bi = si[idx + hm][w];
            float dr = ar - br, di = ai - bi;
            sr[idx][w] = ar + br;  si[idx][w] = ai + bi;
            sr[idx + hm][w] = dr * cv - di * sv;
            si[idx + hm][w] = dr * sv + di * cv;
        }
        __syncwarp();
    }
    __syncthreads();

    const float inv = 1.f / 256.f;
    for (int i = tid; i < 256 * 16; i += 512) {
        int f = i >> 4, tt = i & 15;
        int src = __brev((unsigned)f) >> 24;
        out[((size_t)bc * 256 + f) * 512 + t0 + tt] = sr[src][tt] * inv;
    }
}

// ---------------- launcher ---------------------------------------------------
extern "C" void kernel_launch(void* const* d_in, const int* in_sizes, int n_in,
                              void* d_out, int out_size) {
    const float* x    = (const float*)d_in[0];
    const float* nw   = (const float*)d_in[1];
    const float* nb   = (const float*)d_in[2];
    const float* wihf = (const float*)d_in[3];
    const float* whhf = (const float*)d_in[4];
    const float* bihf = (const float*)d_in[5];
    const float* bhhf = (const float*)d_in[6];
    const float* wihb = (const float*)d_in[7];
    const float* whhb = (const float*)d_in[8];
    const float* bihb = (const float*)d_in[9];
    const float* bhhb = (const float*)d_in[10];
    const float* lw   = (const float*)d_in[11];
    const float* lb   = (const float*)d_in[12];
    float* out = (float*)d_out;

    k_fft_fwd<<<dim3(128, 32), 512>>>(x);
    k_stats1<<<dim3(8, 16, 6), 512>>>();
    k_stats2<<<16, 256>>>();
    k_gates<<<dim3(129, 64), 256>>>(nw, nb, wihf, bihf, bhhf, wihb, bihb, bhhb);
    k_lstm<<<1024, 256>>>(whhf, whhb);
    k_lin_cmul<<<dim3(129, 16, 8), 256>>>(lw, lb);
    k_fft_inv<<<dim3(128, 32), 512>>>(out);
}

// round 4
// speedup vs baseline: 1.5868x; 1.0090x over previous
#include <cuda_runtime.h>
#include <cstdint>

#define BB 8
#define CC 16
#define FDIM 256
#define F2 129
#define TT 512
#define C2 32
#define HH 16
#define NT (BB*TT)

// ---------------- device scratch ----------------
__device__ float g_zraw[(size_t)BB*C2*F2*TT];   // spectrum planes (b, c2, k, t): re c=0..15, im c=16..31
__device__ float g_pre [(size_t)NT*F2*128];     // gate preactivations (n, k, 128): [dir*64 + row]
__device__ float g_h   [(size_t)NT*F2*C2];      // LSTM hidden cat(fwd,bwd): (n, k, 2H)
__device__ float g_P   [(size_t)BB*C2*F2*TT];   // product spectrum planes
__device__ float g_mean[NT];
__device__ float g_rstd[NT];
__device__ float g_psum[NT*6];
__device__ float g_psq [NT*6];

__device__ __forceinline__ float sigf(float x) {
    return __fdividef(1.f, 1.f + __expf(-x));
}
__device__ __forceinline__ float tanhfast(float x) {
    return fmaf(2.f, __fdividef(1.f, 1.f + __expf(-2.f * x)), -1.f);
}
__device__ __forceinline__ unsigned long long pack2(float a, float b) {
    unsigned long long r;
    asm("mov.b64 %0, {%1,%2};" : "=l"(r) : "r"(__float_as_uint(a)), "r"(__float_as_uint(b)));
    return r;
}
__device__ __forceinline__ unsigned long long ffma2(unsigned long long a, unsigned long long b, unsigned long long c) {
    unsigned long long d;
    asm("fma.rn.f32x2 %0, %1, %2, %3;" : "=l"(d) : "l"(a), "l"(b), "l"(c));
    return d;
}
__device__ __forceinline__ int dr4(int k) {   // base-4 digit reversal, 4 digits
    return ((k & 3) << 6) | (((k >> 2) & 3) << 4) | (((k >> 4) & 3) << 2) | ((k >> 6) & 3);
}

// ---------------- K1: forward rfft, radix-4 + real-pair packing -------------
// grid (128, 32), block 512. 16 t-columns packed into 8 complex FFTs.
__global__ void __launch_bounds__(512) k_fft_fwd(const float* __restrict__ x) {
    int bc = blockIdx.x;
    int t0 = blockIdx.y * 16;
    int b = bc >> 4, c = bc & 15;
    __shared__ float sr[256][17], si[256][17];
    __shared__ float2 tw[192];
    int tid = threadIdx.x;

    if (tid < 192) {
        float sv, cv;
        __sincosf(-6.28318530717958647692f * (float)tid * (1.f / 256.f), &sv, &cv);
        tw[tid] = make_float2(cv, sv);
    }
    // pack: col 2j -> real, col 2j+1 -> imag
    for (int i = tid; i < 4096; i += 512) {
        int f = i >> 4, tt = i & 15;
        float v = x[((size_t)bc * 256 + f) * 512 + t0 + tt];
        if (tt & 1) si[f][tt >> 1] = v; else sr[f][tt >> 1] = v;
    }
    __syncthreads();

    int w = tid >> 5, l = tid & 31;
    int jf = w >> 1;                   // FFT index 0..7
    int bfy = ((w & 1) << 5) + l;      // butterfly 0..63
    #pragma unroll
    for (int stage = 0; stage < 4; ++stage) {
        int ms = 6 - 2 * stage;
        int m = 1 << ms;
        int g = bfy >> ms, p = bfy & (m - 1);
        int base = (g << (ms + 2)) + p;
        int e1 = p << (2 * stage);
        float2 w1 = tw[e1], w2 = tw[2 * e1], w3 = tw[3 * e1];
        float ar = sr[base][jf],         ai = si[base][jf];
        float br = sr[base + m][jf],     bi = si[base + m][jf];
        float cr = sr[base + 2*m][jf],   ci = si[base + 2*m][jf];
        float dr = sr[base + 3*m][jf],   di = si[base + 3*m][jf];
        float t0r = ar + cr, t0i = ai + ci;
        float t1r = ar - cr, t1i = ai - ci;
        float t2r = br + dr, t2i = bi + di;
        float t3r = br - dr, t3i = bi - di;
        sr[base][jf] = t0r + t2r;  si[base][jf] = t0i + t2i;
        float u1r = t1r + t3i, u1i = t1i - t3r;          // t1 - j*t3
        sr[base + m][jf]   = u1r * w1.x - u1i * w1.y;
        si[base + m][jf]   = u1r * w1.y + u1i * w1.x;
        float v2r = t0r - t2r, v2i = t0i - t2i;
        sr[base + 2*m][jf] = v2r * w2.x - v2i * w2.y;
        si[base + 2*m][jf] = v2r * w2.y + v2i * w2.x;
        float u3r = t1r - t3i, u3i = t1i + t3r;          // t1 + j*t3
        sr[base + 3*m][jf] = u3r * w3.x - u3i * w3.y;
        si[base + 3*m][jf] = u3r * w3.y + u3i * w3.x;
        __syncthreads();
    }

    // unpack: A[k] = (Z[k]+conj(Z[N-k]))/2 ; B[k] = (Z[k]-conj(Z[N-k]))/(2i)
    float va[3][4];
    int cnt = 0;
    for (int i = tid; i < 1032; i += 512) {
        int k = i >> 3, j = i & 7;
        int ik = dr4(k), im = dr4((256 - k) & 255);
        float zkr = sr[ik][j], zki = si[ik][j];
        float zmr = sr[im][j], zmi = si[im][j];
        va[cnt][0] = 0.5f * (zkr + zmr);    // A re
        va[cnt][1] = 0.5f * (zki - zmi);    // A im
        va[cnt][2] = 0.5f * (zki + zmi);    // B re
        va[cnt][3] = 0.5f * (zmr - zkr);    // B im
        ++cnt;
    }
    __syncthreads();
    cnt = 0;
    for (int i = tid; i < 1032; i += 512) {
        int k = i >> 3, j = i & 7;
        sr[k][2*j]   = va[cnt][0];  si[k][2*j]   = va[cnt][1];
        sr[k][2*j+1] = va[cnt][2];  si[k][2*j+1] = va[cnt][3];
        ++cnt;
    }
    __syncthreads();

    for (int i = tid; i < 2064; i += 512) {
        int k = i >> 4, tt = i & 15;
        g_zraw[(((size_t)b * 32 + c)      * 129 + k) * 512 + t0 + tt] = sr[k][tt];
        g_zraw[(((size_t)b * 32 + 16 + c) * 129 + k) * 512 + t0 + tt] = si[k][tt];
    }
}

// ---------------- K2a: partial stats, grid (8,16,6), block 512 --------------
__global__ void k_stats1() {
    __shared__ float s_sum[16][32], s_sq[16][32];
    int w = threadIdx.x >> 5, l = threadIdx.x & 31;
    int b = blockIdx.x;
    int t = blockIdx.y * 32 + l;
    int part = blockIdx.z;
    const float* base = g_zraw + (size_t)b * 4128 * 512 + t;
    float sum = 0.f, sq = 0.f;
    int e0 = part * 688 + w * 43;
    #pragma unroll 4
    for (int e = e0; e < e0 + 43; ++e) {
        float v = base[(size_t)e * 512];
        sum += v; sq = fmaf(v, v, sq);
    }
    s_sum[w][l] = sum; s_sq[w][l] = sq;
    __syncthreads();
    if (threadIdx.x < 32) {
        int n = b * 512 + blockIdx.y * 32 + threadIdx.x;
        float S = 0.f, Q = 0.f;
        #pragma unroll
        for (int i = 0; i < 16; ++i) { S += s_sum[i][threadIdx.x]; Q += s_sq[i][threadIdx.x]; }
        g_psum[n * 6 + part] = S;
        g_psq [n * 6 + part] = Q;
    }
}

// ---------------- K2b: finalize stats ---------------------------------------
__global__ void k_stats2() {
    int n = blockIdx.x * 256 + threadIdx.x;
    float S = 0.f, Q = 0.f;
    #pragma unroll
    for (int p = 0; p < 6; ++p) { S += g_psum[n * 6 + p]; Q += g_psq[n * 6 + p]; }
    float mean = S * (1.f / 4128.f);
    float var = (Q - S * mean) * (1.f / 4127.f);
    g_mean[n] = mean;
    g_rstd[n] = __fdividef(1.f, sqrtf(fmaxf(var, 0.f)) + 1e-8f);
}

// ---------------- K3: normalize + input-gate GEMM, 8g x 8t tiles ------------
// grid (129, 32), block 256. One k, 128 t-points, all 128 gates per block.
__global__ void __launch_bounds__(256) k_gates(
    const float* __restrict__ nw, const float* __restrict__ nb,
    const float* __restrict__ wihf, const float* __restrict__ bihf, const float* __restrict__ bhhf,
    const float* __restrict__ wihb, const float* __restrict__ bihb, const float* __restrict__ bhhb) {
    int k = blockIdx.x;
    int n0 = blockIdx.y * 128;
    int b = n0 >> 9;
    int tl0 = n0 & 511;
    __shared__ __align__(16) float ys[32][128];
    __shared__ __align__(16) float ws[32][128];
    __shared__ float nws[32], nbs[32], bs[128], means[128], rstds[128];
    int tid = threadIdx.x;

    for (int i = tid; i < 4096; i += 256) {
        int q = i >> 7, tt = i & 127;
        ys[q][tt] = g_zraw[(((size_t)b * 32 + q) * 129 + k) * 512 + tl0 + tt];
    }
    for (int i = tid; i < 4096; i += 256) {
        int q = i >> 7, g = i & 127;
        ws[q][g] = (g < 64) ? wihf[g * 32 + q] : wihb[(g - 64) * 32 + q];
    }
    if (tid < 64) bs[tid] = bihf[tid] + bhhf[tid];
    else if (tid < 128) bs[tid] = bihb[tid - 64] + bhhb[tid - 64];
    if (tid < 32) { nws[tid] = nw[tid * 129 + k]; nbs[tid] = nb[tid * 129 + k]; }
    if (tid >= 128) { means[tid - 128] = g_mean[n0 + tid - 128]; rstds[tid - 128] = g_rstd[n0 + tid - 128]; }
    __syncthreads();

    for (int i = tid; i < 4096; i += 256) {
        int q = i >> 7, tt = i & 127;
        ys[q][tt] = (ys[q][tt] - means[tt]) * rstds[tt] * nws[q] + nbs[q];
    }
    __syncthreads();

    int gg = tid >> 4, tg = tid & 15;
    int g0 = gg << 3, t4 = tg << 3;
    unsigned long long acc[4][8];
    #pragma unroll
    for (int gp = 0; gp < 4; ++gp) {
        unsigned long long bp = pack2(bs[g0 + 2*gp], bs[g0 + 2*gp + 1]);
        #pragma unroll
        for (int t = 0; t < 8; ++t) acc[gp][t] = bp;
    }

    #pragma unroll 8
    for (int q = 0; q < 32; ++q) {
        ulonglong2 wA = *reinterpret_cast<const ulonglong2*>(&ws[q][g0]);       // (g0,g0+1),(g0+2,g0+3)
        ulonglong2 wB = *reinterpret_cast<const ulonglong2*>(&ws[q][g0 + 4]);
        float4 ya = *reinterpret_cast<const float4*>(&ys[q][t4]);
        float4 yb = *reinterpret_cast<const float4*>(&ys[q][t4 + 4]);
        unsigned long long yy[8];
        yy[0] = pack2(ya.x, ya.x); yy[1] = pack2(ya.y, ya.y);
        yy[2] = pack2(ya.z, ya.z); yy[3] = pack2(ya.w, ya.w);
        yy[4] = pack2(yb.x, yb.x); yy[5] = pack2(yb.y, yb.y);
        yy[6] = pack2(yb.z, yb.z); yy[7] = pack2(yb.w, yb.w);
        #pragma unroll
        for (int t = 0; t < 8; ++t) {
            acc[0][t] = ffma2(yy[t], wA.x, acc[0][t]);
            acc[1][t] = ffma2(yy[t], wA.y, acc[1][t]);
            acc[2][t] = ffma2(yy[t], wB.x, acc[2][t]);
            acc[3][t] = ffma2(yy[t], wB.y, acc[3][t]);
        }
    }

    #pragma unroll
    for (int t = 0; t < 8; ++t) {
        size_t row = ((size_t)(n0 + t4 + t) * 129 + k) * 128;
        ulonglong2 v0; v0.x = acc[0][t]; v0.y = acc[1][t];
        ulonglong2 v1; v1.x = acc[2][t]; v1.y = acc[3][t];
        *reinterpret_cast<ulonglong2*>(&g_pre[row + g0]) = v0;
        *reinterpret_cast<ulonglong2*>(&g_pre[row + g0 + 4]) = v1;
    }
}

// ---------------- K4: recurrent-only LSTM, one warp per (seq, dir) ----------
__global__ void __launch_bounds__(256) k_lstm(
    const float* __restrict__ whhf, const float* __restrict__ whhb) {
    int wg = blockIdx.x * 8 + (threadIdx.x >> 5);
    int lane = threadIdx.x & 31;
    int n = wg >> 1, dir = wg & 1;

    const float* whh = dir ? whhb : whhf;
    float wh0[16], wh1[16];
    #pragma unroll
    for (int q = 0; q < 16; ++q) {
        wh0[q] = whh[lane * 16 + q];
        wh1[q] = whh[(lane + 32) * 16 + q];
    }

    const float* pbase = g_pre + (size_t)n * 129 * 128 + dir * 64;
    float* hbase = g_h + (size_t)n * 129 * 32 + dir * 16;

    float h = 0.f, cst = 0.f;
    int k = dir ? 128 : 0;
    int stepd = dir ? -1 : 1;
    float p0 = pbase[k * 128 + lane];
    float p1 = pbase[k * 128 + 32 + lane];

    for (int s = 0; s < 129; ++s) {
        int kn = k + stepd;
        float np0 = 0.f, np1 = 0.f;
        if (s < 128) {
            np0 = pbase[kn * 128 + lane];
            np1 = pbase[kn * 128 + 32 + lane];
        }
        float a0 = p0, a1 = p1, c0 = 0.f, c1 = 0.f;
        #pragma unroll
        for (int q = 0; q < 8; ++q) {
            float hv = __shfl_sync(0xffffffffu, h, q);
            a0 = fmaf(hv, wh0[q], a0);
            a1 = fmaf(hv, wh1[q], a1);
        }
        #pragma unroll
        for (int q = 8; q < 16; ++q) {
            float hv = __shfl_sync(0xffffffffu, h, q);
            c0 = fmaf(hv, wh0[q], c0);
            c1 = fmaf(hv, wh1[q], c1);
        }
        a0 += c0; a1 += c1;
        float fo0 = __shfl_xor_sync(0xffffffffu, a0, 16);
        float fo1 = __shfl_xor_sync(0xffffffffu, a1, 16);
        if (lane < 16) {
            float ig = sigf(a0);
            float gg = tanhfast(a1);
            float ff = sigf(fo0);
            float oo = sigf(fo1);
            cst = fmaf(ff, cst, ig * gg);
            h = oo * tanhfast(cst);
            hbase[k * 32 + lane] = h;
        }
        p0 = np0; p1 = np1; k = kn;
    }
}

// ---------------- K5: linear(2H->2C) + complex multiply ---------------------
__global__ void k_lin_cmul(const float* __restrict__ lw, const float* __restrict__ lb) {
    int k = blockIdx.x, t0 = blockIdx.y * 32, b = blockIdx.z;
    __shared__ float hs[32][33];    // [t][j]
    __shared__ float lws[32][32];   // [c2][j]
    __shared__ float lbs[32];
    __shared__ float yls[32][33];   // [c2][t]
    int tid = threadIdx.x;

    for (int i = tid; i < 1024; i += 256) lws[i >> 5][i & 31] = lw[i];
    if (tid < 32) lbs[tid] = lb[tid];
    for (int i = tid; i < 1024; i += 256) {
        int tt = i >> 5, j = i & 31;
        hs[tt][j] = g_h[(((size_t)(b * 512 + t0 + tt)) * 129 + k) * 32 + j];
    }
    __syncthreads();

    int tt = tid & 31, g = tid >> 5;
    #pragma unroll
    for (int ci = 0; ci < 4; ++ci) {
        int c2 = g + ci * 8;
        float acc = lbs[c2];
        #pragma unroll
        for (int j = 0; j < 32; ++j) acc = fmaf(hs[tt][j], lws[c2][j], acc);
        yls[c2][tt] = acc;
    }
    __syncthreads();

    size_t basez = ((size_t)(b * 32) * 129 + k) * 512 + t0 + tt;
    const size_t ps = (size_t)129 * 512;
    #pragma unroll
    for (int ci = 0; ci < 4; ++ci) {
        int c2 = g + ci * 8;
        if (c2 < 16) {
            float xr = g_zraw[basez + (size_t)c2 * ps];
            float xi = g_zraw[basez + (size_t)(c2 + 16) * ps];
            float yr = yls[c2][tt], yi = yls[c2 + 16][tt];
            g_P[basez + (size_t)c2 * ps] = yr * xr - yi * xi;
        } else {
            int c = c2 - 16;
            float xr = g_zraw[basez + (size_t)c * ps];
            float xi = g_zraw[basez + (size_t)c2 * ps];
            float yr = yls[c][tt], yi = yls[c2][tt];
            g_P[basez + (size_t)c2 * ps] = yr * xi + yi * xr;
        }
    }
}

// ---------------- K6: irfft, radix-4 + spectrum-pair packing ----------------
// grid (128, 32), block 512. 16 t-columns packed into 8 complex inverse FFTs.
__global__ void __launch_bounds__(512) k_fft_inv(float* __restrict__ out) {
    int bc = blockIdx.x;
    int t0 = blockIdx.y * 16;
    int b = bc >> 4, c = bc & 15;
    __shared__ float sr[256][17], si[256][17];
    __shared__ float2 tw[192];
    int tid = threadIdx.x;

    if (tid < 192) {
        float sv, cv;
        __sincosf(6.28318530717958647692f * (float)tid * (1.f / 256.f), &sv, &cv);
        tw[tid] = make_float2(cv, sv);
    }
    for (int i = tid; i < 2064; i += 512) {
        int k = i >> 4, tt = i & 15;
        sr[k][tt] = g_P[(((size_t)b * 32 + c)      * 129 + k) * 512 + t0 + tt];
        si[k][tt] = g_P[(((size_t)b * 32 + 16 + c) * 129 + k) * 512 + t0 + tt];
    }
    __syncthreads();

    // build packed Z = Pa_ext + i*Pb_ext, zeroing imag of bins 0 and 128
    float vz[4][2];
    int cnt = 0;
    for (int i = tid; i < 2048; i += 512) {
        int row = i >> 3, j = i & 7;
        float zr, zi;
        if (row <= 128) {
            float par = sr[row][2*j];
            float pai = (row == 0 || row == 128) ? 0.f : si[row][2*j];
            float pbr = sr[row][2*j+1];
            float pbi = (row == 0 || row == 128) ? 0.f : si[row][2*j+1];
            zr = par - pbi; zi = pai + pbr;
        } else {
            int m = 256 - row;
            float par = sr[m][2*j], pai = si[m][2*j];
            float pbr = sr[m][2*j+1], pbi = si[m][2*j+1];
            zr = par + pbi; zi = pbr - pai;
        }
        vz[cnt][0] = zr; vz[cnt][1] = zi; ++cnt;
    }
    __syncthreads();
    cnt = 0;
    for (int i = tid; i < 2048; i += 512) {
        int row = i >> 3, j = i & 7;
        sr[row][j] = vz[cnt][0];
        si[row][j] = vz[cnt][1];
        ++cnt;
    }
    __syncthreads();

    int w = tid >> 5, l = tid & 31;
    int jf = w >> 1;
    int bfy = ((w & 1) << 5) + l;
    #pragma unroll
    for (int stage = 0; stage < 4; ++stage) {
        int ms = 6 - 2 * stage;
        int m = 1 << ms;
        int g = bfy >> ms, p = bfy & (m - 1);
        int base = (g << (ms + 2)) + p;
        int e1 = p << (2 * stage);
        float2 w1 = tw[e1], w2 = tw[2 * e1], w3 = tw[3 * e1];
        float ar = sr[base][jf],         ai = si[base][jf];
        float br = sr[base + m][jf],     bi = si[base + m][jf];
        float cr = sr[base + 2*m][jf],   ci = si[base + 2*m][jf];
        float dr = sr[base + 3*m][jf],   di = si[base + 3*m][jf];
        float t0r = ar + cr, t0i = ai + ci;
        float t1r = ar - cr, t1i = ai - ci;
        float t2r = br + dr, t2i = bi + di;
        float t3r = br - dr, t3i = bi - di;
        sr[base][jf] = t0r + t2r;  si[base][jf] = t0i + t2i;
        float u1r = t1r - t3i, u1i = t1i + t3r;          // inverse: t1 + j*t3
        sr[base + m][jf]   = u1r * w1.x - u1i * w1.y;
        si[base + m][jf]   = u1r * w1.y + u1i * w1.x;
        float v2r = t0r - t2r, v2i = t0i - t2i;
        sr[base + 2*m][jf] = v2r * w2.x - v2i * w2.y;
        si[base + 2*m][jf] = v2r * w2.y + v2i * w2.x;
        float u3r = t1r + t3i, u3i = t1i - t3r;          // inverse: t1 - j*t3
        sr[base + 3*m][jf] = u3r * w3.x - u3i * w3.y;
        si[base + 3*m][jf] = u3r * w3.y + u3i * w3.x;
        __syncthreads();
    }

    const float inv = 1.f / 256.f;
    for (int i = tid; i < 4096; i += 512) {
        int f = i >> 4, tt = i & 15;
        int j = tt >> 1;
        int src = dr4(f);
        float v = (tt & 1) ? si[src][j] : sr[src][j];
        out[((size_t)bc * 256 + f) * 512 + t0 + tt] = v * inv;
    }
}

// ---------------- launcher ---------------------------------------------------
extern "C" void kernel_launch(void* const* d_in, const int* in_sizes, int n_in,
                              void* d_out, int out_size) {
    const float* x    = (const float*)d_in[0];
    const float* nw   = (const float*)d_in[1];
    const float* nb   = (const float*)d_in[2];
    const float* wihf = (const float*)d_in[3];
    const float* whhf = (const float*)d_in[4];
    const float* bihf = (const float*)d_in[5];
    const float* bhhf = (const float*)d_in[6];
    const float* wihb = (const float*)d_in[7];
    const float* whhb = (const float*)d_in[8];
    const float* bihb = (const float*)d_in[9];
    const float* bhhb = (const float*)d_in[10];
    const float* lw   = (const float*)d_in[11];
    const float* lb   = (const float*)d_in[12];
    float* out = (float*)d_out;

    k_fft_fwd<<<dim3(128, 32), 512>>>(x);
    k_stats1<<<dim3(8, 16, 6), 512>>>();
    k_stats2<<<16, 256>>>();
    k_gates<<<dim3(129, 32), 256>>>(nw, nb, wihf, bihf, bhhf, wihb, bihb, bhhb);
    k_lstm<<<1024, 256>>>(whhf, whhb);
    k_lin_cmul<<<dim3(129, 16, 8), 256>>>(lw, lb);
    k_fft_inv<<<dim3(128, 32), 512>>>(out);
}

// round 7
// speedup vs baseline: 1.7608x; 1.1097x over previous
#include <cuda_runtime.h>
#include <cstdint>

#define BB 8
#define CC 16
#define FDIM 256
#define F2 129
#define TT 512
#define C2 32
#define HH 16
#define NT (BB*TT)

// ---------------- device scratch ----------------
__device__ float g_zraw[(size_t)BB*C2*F2*TT];   // spectrum planes (b, c2, k, t): re c=0..15, im c=16..31
__device__ float g_pre [(size_t)NT*F2*128];     // gate preactivations (n, k, 128): [dir*64 + row]
__device__ float g_h   [(size_t)NT*F2*C2];      // LSTM hidden cat(fwd,bwd): (n, k, 2H)
__device__ float g_P   [(size_t)BB*C2*F2*TT];   // product spectrum planes
__device__ float g_mean[NT];
__device__ float g_rstd[NT];
__device__ float g_psum[NT*6];
__device__ float g_psq [NT*6];

__device__ __forceinline__ float sigf(float x) {
    return __fdividef(1.f, 1.f + __expf(-x));
}
__device__ __forceinline__ float tanhfast(float x) {
    return fmaf(2.f, __fdividef(1.f, 1.f + __expf(-2.f * x)), -1.f);
}
__device__ __forceinline__ unsigned long long pack2(float a, float b) {
    unsigned long long r;
    asm("mov.b64 %0, {%1,%2};" : "=l"(r) : "r"(__float_as_uint(a)), "r"(__float_as_uint(b)));
    return r;
}
__device__ __forceinline__ void unpack2(unsigned long long v, float& a, float& b) {
    unsigned int lo, hi;
    asm("mov.b64 {%0,%1}, %2;" : "=r"(lo), "=r"(hi) : "l"(v));
    a = __uint_as_float(lo); b = __uint_as_float(hi);
}
__device__ __forceinline__ unsigned long long ffma2(unsigned long long a, unsigned long long b, unsigned long long c) {
    unsigned long long d;
    asm("fma.rn.f32x2 %0, %1, %2, %3;" : "=l"(d) : "l"(a), "l"(b), "l"(c));
    return d;
}
__device__ __forceinline__ int dr4(int k) {   // base-4 digit reversal, 4 digits
    return ((k & 3) << 6) | (((k >> 2) & 3) << 4) | (((k >> 4) & 3) << 2) | ((k >> 6) & 3);
}

// ---------------- K1: forward rfft, warp-private radix-4, real-pair packed --
// grid (128, 16), block 512 (16 warps). 32 t-cols -> 16 complex FFTs, one/warp.
__global__ void __launch_bounds__(512) k_fft_fwd(const float* __restrict__ x) {
    int bc = blockIdx.x;
    int t0 = blockIdx.y * 32;
    int b = bc >> 4, c = bc & 15;
    __shared__ float sr[258][17], si[258][17];
    __shared__ float2 tw[192];
    int tid = threadIdx.x;
    int w = tid >> 5, l = tid & 31;

    if (tid < 192) {
        float sv, cv;
        __sincosf(-6.28318530717958647692f * (float)tid * (1.f / 256.f), &sv, &cv);
        tw[tid] = make_float2(cv, sv);
    }
    // load: col 2j -> real, col 2j+1 -> imag (128B-coalesced global reads)
    for (int i = tid; i < 8192; i += 512) {
        int f = i >> 5, tt = i & 31;
        float v = x[((size_t)bc * 256 + f) * 512 + t0 + tt];
        if (tt & 1) si[f][tt >> 1] = v; else sr[f][tt >> 1] = v;
    }
    __syncthreads();

    // 4 radix-4 DIF stages, warp-private column w
    #pragma unroll
    for (int stage = 0; stage < 4; ++stage) {
        int ms = 6 - 2 * stage;
        int m = 1 << ms;
        #pragma unroll
        for (int half = 0; half < 2; ++half) {
            int bfy = l + 32 * half;
            int g = bfy >> ms, p = bfy & (m - 1);
            int base = (g << (ms + 2)) + p;
            int e1 = p << (2 * stage);
            float2 w1 = tw[e1], w2 = tw[2 * e1], w3 = tw[3 * e1];
            float ar = sr[base][w],        ai = si[base][w];
            float br = sr[base + m][w],    bi = si[base + m][w];
            float cr = sr[base + 2*m][w],  ci = si[base + 2*m][w];
            float dr = sr[base + 3*m][w],  di = si[base + 3*m][w];
            float t0r = ar + cr, t0i = ai + ci;
            float t1r = ar - cr, t1i = ai - ci;
            float t2r = br + dr, t2i = bi + di;
            float t3r = br - dr, t3i = bi - di;
            sr[base][w] = t0r + t2r;  si[base][w] = t0i + t2i;
            float u1r = t1r + t3i, u1i = t1i - t3r;          // t1 - j*t3
            sr[base + m][w]   = u1r * w1.x - u1i * w1.y;
            si[base + m][w]   = u1r * w1.y + u1i * w1.x;
            float v2r = t0r - t2r, v2i = t0i - t2i;
            sr[base + 2*m][w] = v2r * w2.x - v2i * w2.y;
            si[base + 2*m][w] = v2r * w2.y + v2i * w2.x;
            float u3r = t1r - t3i, u3i = t1i + t3r;          // t1 + j*t3
            sr[base + 3*m][w] = u3r * w3.x - u3i * w3.y;
            si[base + 3*m][w] = u3r * w3.y + u3i * w3.x;
        }
        __syncwarp();
    }

    // unpack A/B (warp-local): A[k]=(Z[k]+conj(Z[N-k]))/2, B=(Z[k]-conj(Z[N-k]))/(2i)
    float va[5][4];
    #pragma unroll
    for (int r = 0; r < 4; ++r) {
        int k = l + 32 * r;
        int ik = dr4(k), im = dr4((256 - k) & 255);
        float zkr = sr[ik][w], zki = si[ik][w];
        float zmr = sr[im][w], zmi = si[im][w];
        va[r][0] = 0.5f * (zkr + zmr);
        va[r][1] = 0.5f * (zki - zmi);
        va[r][2] = 0.5f * (zki + zmi);
        va[r][3] = 0.5f * (zmr - zkr);
    }
    if (l == 0) {
        int ik = dr4(128);
        float zkr = sr[ik][w], zki = si[ik][w];
        va[4][0] = zkr; va[4][1] = 0.f;
        va[4][2] = zki; va[4][3] = 0.f;
    }
    __syncwarp();
    // rows 0..128: A ; rows 129..257: B
    #pragma unroll
    for (int r = 0; r < 4; ++r) {
        int k = l + 32 * r;
        sr[k][w] = va[r][0];        si[k][w] = va[r][1];
        sr[129 + k][w] = va[r][2];  si[129 + k][w] = va[r][3];
    }
    if (l == 0) {
        sr[128][w] = va[4][0];       si[128][w] = va[4][1];
        sr[129 + 128][w] = va[4][2]; si[129 + 128][w] = va[4][3];
    }
    __syncthreads();

    // coalesced store (128B rows)
    for (int i = tid; i < 4128; i += 512) {
        int k = i >> 5, tt = i & 31;
        int j = tt >> 1;
        int row = (tt & 1) ? (129 + k) : k;
        g_zraw[(((size_t)b * 32 + c)      * 129 + k) * 512 + t0 + tt] = sr[row][j];
        g_zraw[(((size_t)b * 32 + 16 + c) * 129 + k) * 512 + t0 + tt] = si[row][j];
    }
}

// ---------------- K2a: partial stats, grid (8,16,6), block 512 --------------
__global__ void k_stats1() {
    __shared__ float s_sum[16][32], s_sq[16][32];
    int w = threadIdx.x >> 5, l = threadIdx.x & 31;
    int b = blockIdx.x;
    int t = blockIdx.y * 32 + l;
    int part = blockIdx.z;
    const float* base = g_zraw + (size_t)b * 4128 * 512 + t;
    float sum = 0.f, sq = 0.f;
    int e0 = part * 688 + w * 43;
    #pragma unroll 4
    for (int e = e0; e < e0 + 43; ++e) {
        float v = base[(size_t)e * 512];
        sum += v; sq = fmaf(v, v, sq);
    }
    s_sum[w][l] = sum; s_sq[w][l] = sq;
    __syncthreads();
    if (threadIdx.x < 32) {
        int n = b * 512 + blockIdx.y * 32 + threadIdx.x;
        float S = 0.f, Q = 0.f;
        #pragma unroll
        for (int i = 0; i < 16; ++i) { S += s_sum[i][threadIdx.x]; Q += s_sq[i][threadIdx.x]; }
        g_psum[n * 6 + part] = S;
        g_psq [n * 6 + part] = Q;
    }
}

// ---------------- K2b: finalize stats ---------------------------------------
__global__ void k_stats2() {
    int n = blockIdx.x * 256 + threadIdx.x;
    float S = 0.f, Q = 0.f;
    #pragma unroll
    for (int p = 0; p < 6; ++p) { S += g_psum[n * 6 + p]; Q += g_psq[n * 6 + p]; }
    float mean = S * (1.f / 4128.f);
    float var = (Q - S * mean) * (1.f / 4127.f);
    g_mean[n] = mean;
    g_rstd[n] = __fdividef(1.f, sqrtf(fmaxf(var, 0.f)) + 1e-8f);
}

// ---------------- K3: normalize + input-gate GEMM (R3 config, 8g x 4t) ------
// grid (129, 64), block 256.
__global__ void __launch_bounds__(256) k_gates(
    const float* __restrict__ nw, const float* __restrict__ nb,
    const float* __restrict__ wihf, const float* __restrict__ bihf, const float* __restrict__ bhhf,
    const float* __restrict__ wihb, const float* __restrict__ bihb, const float* __restrict__ bhhb) {
    int k = blockIdx.x;
    int n0 = blockIdx.y * 64;
    int b = n0 >> 9, tl0 = n0 & 511;
    __shared__ __align__(16) float ys[32][68];
    __shared__ __align__(16) union {
        unsigned long long w[32][130];
        float stage[64][132];
    } u;
    __shared__ float nws[32], nbs[32], means[64], rstds[64], bs[128];
    int tid = threadIdx.x;

    for (int i = tid; i < 2048; i += 256) {
        int c2 = i >> 6, tt = i & 63;
        ys[c2][tt] = g_zraw[(((size_t)b * 32 + c2) * 129 + k) * 512 + tl0 + tt];
    }
    for (int i = tid; i < 2048; i += 256) {
        int r = i >> 5, q = i & 31;
        float wf = wihf[i]; u.w[q][r] = pack2(wf, wf);
        float wb = wihb[i]; u.w[q][64 + r] = pack2(wb, wb);
    }
    if (tid < 64) bs[tid] = bihf[tid] + bhhf[tid];
    else if (tid < 128) bs[tid] = bihb[tid - 64] + bhhb[tid - 64];
    if (tid < 32) { nws[tid] = nw[tid * 129 + k]; nbs[tid] = nb[tid * 129 + k]; }
    if (tid >= 32 && tid < 96) { means[tid - 32] = g_mean[n0 + tid - 32]; rstds[tid - 32] = g_rstd[n0 + tid - 32]; }
    __syncthreads();

    for (int i = tid; i < 2048; i += 256) {
        int c2 = i >> 6, tt = i & 63;
        ys[c2][tt] = (ys[c2][tt] - means[tt]) * rstds[tt] * nws[c2] + nbs[c2];
    }
    __syncthreads();

    int gg = tid >> 4, tg = tid & 15;
    int g0 = gg << 3, t4 = tg << 2;
    unsigned long long acc[8][2];
    #pragma unroll
    for (int j = 0; j < 8; ++j) {
        float bj = bs[g0 + j];
        acc[j][0] = pack2(bj, bj);
        acc[j][1] = acc[j][0];
    }
    #pragma unroll 4
    for (int q = 0; q < 32; ++q) {
        ulonglong2 y2 = *reinterpret_cast<const ulonglong2*>(&ys[q][t4]);
        const ulonglong2* wp = reinterpret_cast<const ulonglong2*>(&u.w[q][g0]);
        ulonglong2 w01 = wp[0], w23 = wp[1], w45 = wp[2], w67 = wp[3];
        acc[0][0] = ffma2(y2.x, w01.x, acc[0][0]);  acc[0][1] = ffma2(y2.y, w01.x, acc[0][1]);
        acc[1][0] = ffma2(y2.x, w01.y, acc[1][0]);  acc[1][1] = ffma2(y2.y, w01.y, acc[1][1]);
        acc[2][0] = ffma2(y2.x, w23.x, acc[2][0]);  acc[2][1] = ffma2(y2.y, w23.x, acc[2][1]);
        acc[3][0] = ffma2(y2.x, w23.y, acc[3][0]);  acc[3][1] = ffma2(y2.y, w23.y, acc[3][1]);
        acc[4][0] = ffma2(y2.x, w45.x, acc[4][0]);  acc[4][1] = ffma2(y2.y, w45.x, acc[4][1]);
        acc[5][0] = ffma2(y2.x, w45.y, acc[5][0]);  acc[5][1] = ffma2(y2.y, w45.y, acc[5][1]);
        acc[6][0] = ffma2(y2.x, w67.x, acc[6][0]);  acc[6][1] = ffma2(y2.y, w67.x, acc[6][1]);
        acc[7][0] = ffma2(y2.x, w67.y, acc[7][0]);  acc[7][1] = ffma2(y2.y, w67.y, acc[7][1]);
    }
    __syncthreads();

    #pragma unroll
    for (int j = 0; j < 8; ++j) {
        float v00, v01, v10, v11;
        unpack2(acc[j][0], v00, v01);
        unpack2(acc[j][1], v10, v11);
        u.stage[t4 + 0][g0 + j] = v00;
        u.stage[t4 + 1][g0 + j] = v01;
        u.stage[t4 + 2][g0 + j] = v10;
        u.stage[t4 + 3][g0 + j] = v11;
    }
    __syncthreads();

    for (int i = tid; i < 2048; i += 256) {
        int tt = i >> 5, g4 = (i & 31) << 2;
        float4 v = *reinterpret_cast<const float4*>(&u.stage[tt][g4]);
        *reinterpret_cast<float4*>(&g_pre[((size_t)(n0 + tt) * 129 + k) * 128 + g4]) = v;
    }
}

// ---------------- K4: recurrent-only LSTM, one warp per (seq, dir) ----------
__global__ void __launch_bounds__(256) k_lstm(
    const float* __restrict__ whhf, const float* __restrict__ whhb) {
    int wg = blockIdx.x * 8 + (threadIdx.x >> 5);
    int lane = threadIdx.x & 31;
    int n = wg >> 1, dir = wg & 1;

    const float* whh = dir ? whhb : whhf;
    float wh0[16], wh1[16];
    #pragma unroll
    for (int q = 0; q < 16; ++q) {
        wh0[q] = whh[lane * 16 + q];
        wh1[q] = whh[(lane + 32) * 16 + q];
    }

    const float* pbase = g_pre + (size_t)n * 129 * 128 + dir * 64;
    float* hbase = g_h + (size_t)n * 129 * 32 + dir * 16;

    float h = 0.f, cst = 0.f;
    int k = dir ? 128 : 0;
    int stepd = dir ? -1 : 1;
    float p0 = pbase[k * 128 + lane];
    float p1 = pbase[k * 128 + 32 + lane];

    for (int s = 0; s < 129; ++s) {
        int kn = k + stepd;
        float np0 = 0.f, np1 = 0.f;
        if (s < 128) {
            np0 = pbase[kn * 128 + lane];
            np1 = pbase[kn * 128 + 32 + lane];
        }
        float a0 = p0, a1 = p1, c0 = 0.f, c1 = 0.f;
        #pragma unroll
        for (int q = 0; q < 8; ++q) {
            float hv = __shfl_sync(0xffffffffu, h, q);
            a0 = fmaf(hv, wh0[q], a0);
            a1 = fmaf(hv, wh1[q], a1);
        }
        #pragma unroll
        for (int q = 8; q < 16; ++q) {
            float hv = __shfl_sync(0xffffffffu, h, q);
            c0 = fmaf(hv, wh0[q], c0);
            c1 = fmaf(hv, wh1[q], c1);
        }
        a0 += c0; a1 += c1;
        float fo0 = __shfl_xor_sync(0xffffffffu, a0, 16);
        float fo1 = __shfl_xor_sync(0xffffffffu, a1, 16);
        if (lane < 16) {
            float ig = sigf(a0);
            float gg = tanhfast(a1);
            float ff = sigf(fo0);
            float oo = sigf(fo1);
            cst = fmaf(ff, cst, ig * gg);
            h = oo * tanhfast(cst);
            hbase[k * 32 + lane] = h;
        }
        p0 = np0; p1 = np1; k = kn;
    }
}

// ---------------- K5: linear(2H->2C) + complex multiply ---------------------
__global__ void k_lin_cmul(const float* __restrict__ lw, const float* __restrict__ lb) {
    int k = blockIdx.x, t0 = blockIdx.y * 32, b = blockIdx.z;
    __shared__ float hs[32][33];    // [t][j]
    __shared__ float lws[32][32];   // [c2][j]
    __shared__ float lbs[32];
    __shared__ float yls[32][33];   // [c2][t]
    int tid = threadIdx.x;

    for (int i = tid; i < 1024; i += 256) lws[i >> 5][i & 31] = lw[i];
    if (tid < 32) lbs[tid] = lb[tid];
    for (int i = tid; i < 1024; i += 256) {
        int tt = i >> 5, j = i & 31;
        hs[tt][j] = g_h[(((size_t)(b * 512 + t0 + tt)) * 129 + k) * 32 + j];
    }
    __syncthreads();

    int tt = tid & 31, g = tid >> 5;
    #pragma unroll
    for (int ci = 0; ci < 4; ++ci) {
        int c2 = g + ci * 8;
        float acc = lbs[c2];
        #pragma unroll
        for (int j = 0; j < 32; ++j) acc = fmaf(hs[tt][j], lws[c2][j], acc);
        yls[c2][tt] = acc;
    }
    __syncthreads();

    size_t basez = ((size_t)(b * 32) * 129 + k) * 512 + t0 + tt;
    const size_t ps = (size_t)129 * 512;
    #pragma unroll
    for (int ci = 0; ci < 4; ++ci) {
        int c2 = g + ci * 8;
        if (c2 < 16) {
            float xr = g_zraw[basez + (size_t)c2 * ps];
            float xi = g_zraw[basez + (size_t)(c2 + 16) * ps];
            float yr = yls[c2][tt], yi = yls[c2 + 16][tt];
            g_P[basez + (size_t)c2 * ps] = yr * xr - yi * xi;
        } else {
            int c = c2 - 16;
            float xr = g_zraw[basez + (size_t)c * ps];
            float xi = g_zraw[basez + (size_t)c2 * ps];
            float yr = yls[c][tt], yi = yls[c2][tt];
            g_P[basez + (size_t)c2 * ps] = yr * xi + yi * xr;
        }
    }
}

// ---------------- K6: irfft, warp-private radix-4, spectrum-pair packed -----
// grid (128, 16), block 512.
__global__ void __launch_bounds__(512) k_fft_inv(float* __restrict__ out) {
    int bc = blockIdx.x;
    int t0 = blockIdx.y * 32;
    int b = bc >> 4, c = bc & 15;
    __shared__ float sr[258][17], si[258][17];
    __shared__ float2 tw[192];
    int tid = threadIdx.x;
    int w = tid >> 5, l = tid & 31;

    if (tid < 192) {
        float sv, cv;
        __sincosf(6.28318530717958647692f * (float)tid * (1.f / 256.f), &sv, &cv);
        tw[tid] = make_float2(cv, sv);
    }
    // load: even t-cols (Pa) -> rows 0..128, odd (Pb) -> rows 129..257
    for (int i = tid; i < 4128; i += 512) {
        int k = i >> 5, tt = i & 31;
        int j = tt >> 1;
        int row = (tt & 1) ? (129 + k) : k;
        sr[row][j] = g_P[(((size_t)b * 32 + c)      * 129 + k) * 512 + t0 + tt];
        si[row][j] = g_P[(((size_t)b * 32 + 16 + c) * 129 + k) * 512 + t0 + tt];
    }
    __syncthreads();

    // combine Z = Pa_ext + i*Pb_ext (warp-local, read-all-then-write)
    float vz[8][2];
    #pragma unroll
    for (int r = 0; r < 8; ++r) {
        int row = l + 32 * r;
        float zr, zi;
        if (row <= 128) {
            float par = sr[row][w];
            float pai = (row == 0 || row == 128) ? 0.f : si[row][w];
            float pbr = sr[129 + row][w];
            float pbi = (row == 0 || row == 128) ? 0.f : si[129 + row][w];
            zr = par - pbi; zi = pai + pbr;
        } else {
            int m = 256 - row;
            float par = sr[m][w], pai = si[m][w];
            float pbr = sr[129 + m][w], pbi = si[129 + m][w];
            zr = par + pbi; zi = pbr - pai;
        }
        vz[r][0] = zr; vz[r][1] = zi;
    }
    __syncwarp();
    #pragma unroll
    for (int r = 0; r < 8; ++r) {
        int row = l + 32 * r;
        sr[row][w] = vz[r][0];
        si[row][w] = vz[r][1];
    }
    __syncwarp();

    // inverse radix-4 DIF stages, warp-private
    #pragma unroll
    for (int stage = 0; stage < 4; ++stage) {
        int ms = 6 - 2 * stage;
        int m = 1 << ms;
        #pragma unroll
        for (int half = 0; half < 2; ++half) {
            int bfy = l + 32 * half;
            int g = bfy >> ms, p = bfy & (m - 1);
            int base = (g << (ms + 2)) + p;
            int e1 = p << (2 * stage);
            float2 w1 = tw[e1], w2 = tw[2 * e1], w3 = tw[3 * e1];
            float ar = sr[base][w],        ai = si[base][w];
            float br = sr[base + m][w],    bi = si[base + m][w];
            float cr = sr[base + 2*m][w],  ci = si[base + 2*m][w];
            float dr = sr[base + 3*m][w],  di = si[base + 3*m][w];
            float t0r = ar + cr, t0i = ai + ci;
            float t1r = ar - cr, t1i = ai - ci;
            float t2r = br + dr, t2i = bi + di;
            float t3r = br - dr, t3i = bi - di;
            sr[base][w] = t0r + t2r;  si[base][w] = t0i + t2i;
            float u1r = t1r - t3i, u1i = t1i + t3r;          // inverse: t1 + j*t3
            sr[base + m][w]   = u1r * w1.x - u1i * w1.y;
            si[base + m][w]   = u1r * w1.y + u1i * w1.x;
            float v2r = t0r - t2r, v2i = t0i - t2i;
            sr[base + 2*m][w] = v2r * w2.x - v2i * w2.y;
            si[base + 2*m][w] = v2r * w2.y + v2i * w2.x;
            float u3r = t1r + t3i, u3i = t1i - t3r;          // inverse: t1 - j*t3
            sr[base + 3*m][w] = u3r * w3.x - u3i * w3.y;
            si[base + 3*m][w] = u3r * w3.y + u3i * w3.x;
        }
        __syncwarp();
    }
    __syncthreads();

    const float inv = 1.f / 256.f;
    for (int i = tid; i < 8192; i += 512) {
        int f = i >> 5, tt = i & 31;
        int j = tt >> 1;
        int src = dr4(f);
        float v = (tt & 1) ? si[src][j] : sr[src][j];
        out[((size_t)bc * 256 + f) * 512 + t0 + tt] = v * inv;
    }
}

// ---------------- launcher ---------------------------------------------------
extern "C" void kernel_launch(void* const* d_in, const int* in_sizes, int n_in,
                              void* d_out, int out_size) {
    const float* x    = (const float*)d_in[0];
    const float* nw   = (const float*)d_in[1];
    const float* nb   = (const float*)d_in[2];
    const float* wihf = (const float*)d_in[3];
    const float* whhf = (const float*)d_in[4];
    const float* bihf = (const float*)d_in[5];
    const float* bhhf = (const float*)d_in[6];
    const float* wihb = (const float*)d_in[7];
    const float* whhb = (const float*)d_in[8];
    const float* bihb = (const float*)d_in[9];
    const float* bhhb = (const float*)d_in[10];
    const float* lw   = (const float*)d_in[11];
    const float* lb   = (const float*)d_in[12];
    float* out = (float*)d_out;

    k_fft_fwd<<<dim3(128, 16), 512>>>(x);
    k_stats1<<<dim3(8, 16, 6), 512>>>();
    k_stats2<<<16, 256>>>();
    k_gates<<<dim3(129, 64), 256>>>(nw, nb, wihf, bihf, bhhf, wihb, bihb, bhhb);
    k_lstm<<<1024, 256>>>(whhf, whhb);
    k_lin_cmul<<<dim3(129, 16, 8), 256>>>(lw, lb);
    k_fft_inv<<<dim3(128, 16), 512>>>(out);
}